// round 3
// baseline (speedup 1.0000x reference)
#include <cuda_runtime.h>
#include <cstdint>

// PPEG: out[b, 0, c]   = x[b, 0, c]                       (cls token)
//       out[b, 1+p, c] = combined 7x7 depthwise conv of the 64x64 map
// Combined weights: w_eff = w7 + pad(w5) + pad(w3) + identity@center
// Combined bias:    b7 + b5 + b3

#define CH   512
#define HW   64
#define NTOK 4097

__device__ float g_weff[49 * CH];   // [tap][channel]
__device__ float g_bsum[CH];

// packed f32x2 FMA (sm_103a FFMA2 — only reachable via PTX)
__device__ __forceinline__ unsigned long long ffma2(unsigned long long a,
                                                    unsigned long long b,
                                                    unsigned long long c) {
    unsigned long long d;
    asm("fma.rn.f32x2 %0, %1, %2, %3;" : "=l"(d) : "l"(a), "l"(b), "l"(c));
    return d;
}

// ---------------------------------------------------------------------------
// Kernel 1: weight fold + bias + cls copy, all in one launch.
//   blocks   0..97 : fold (25088 threads, idx -> c = idx/49, t = idx%49;
//                    t fastest => coalesced w7 reads)
//   blocks  98..99 : bias sum
//   blocks 100..131: cls-token passthrough (16*512 floats)
__global__ void ppeg_prep(const float* __restrict__ w7, const float* __restrict__ b7,
                          const float* __restrict__ w5, const float* __restrict__ b5,
                          const float* __restrict__ w3, const float* __restrict__ b3,
                          const float* __restrict__ x, float* __restrict__ out) {
    const int bid = blockIdx.x;
    const int tid = threadIdx.x;
    if (bid < 98) {
        const int i = bid * 256 + tid;        // 0 .. 25087 = 512*49
        const int c = i / 49;
        const int t = i % 49;
        const int ky = t / 7, kx = t % 7;
        float v = w7[c * 49 + t];
        if (ky >= 1 && ky <= 5 && kx >= 1 && kx <= 5)
            v += w5[c * 25 + (ky - 1) * 5 + (kx - 1)];
        if (ky >= 2 && ky <= 4 && kx >= 2 && kx <= 4)
            v += w3[c * 9 + (ky - 2) * 3 + (kx - 2)];
        if (t == 24) v += 1.0f;               // identity (residual) term
        g_weff[t * CH + c] = v;
    } else if (bid < 100) {
        const int c = (bid - 98) * 256 + tid;
        g_bsum[c] = b7[c] + b5[c] + b3[c];
    } else {
        const int j = (bid - 100) * 256 + tid;   // 0 .. 8191
        const int b = j >> 9;
        const int cc = j & 511;
        const size_t off = (size_t)b * NTOK * CH + cc;
        out[off] = x[off];
    }
}

// ---------------------------------------------------------------------------
// Kernel 2: combined 7x7 depthwise conv.
//   lane  = channel pair (64 ch per block) -> 256B coalesced accesses
//   thread= 8x2 output pixels; warp layout 2x8 -> block tile 16x16 pixels
//   halo redundancy (22/16)^2 = 1.89x  (was 3.4x with 16x4 tiles)
//   Double-buffered row windows hide L2 latency under the FFMA2 stream.
__global__ void __launch_bounds__(512, 1)
ppeg_conv(const float* __restrict__ x, float* __restrict__ out) {
    const int lane = threadIdx.x & 31;
    const int warp = threadIdx.x >> 5;
    const int wx = warp & 1;
    const int wy = warp >> 1;                  // 0..7
    const int x0 = blockIdx.x * 16 + wx * 8;   // RX=8 output cols per thread
    const int y0 = blockIdx.y * 16 + wy * 2;   // RY=2 output rows per thread
    const int b  = blockIdx.z >> 3;
    const int cg = blockIdx.z & 7;
    const int cb = cg * 64;
    const int c  = cb + lane * 2;

    // Stage this channel group's combined weights + bias into SMEM.
    __shared__ __align__(16) float sw[49 * 64];
    __shared__ __align__(16) float sb[64];
    for (int i = threadIdx.x; i < 49 * 64; i += 512) {
        const int t  = i >> 6;
        const int cc = i & 63;
        sw[i] = g_weff[t * CH + cb + cc];
    }
    if (threadIdx.x < 64) sb[threadIdx.x] = g_bsum[cb + threadIdx.x];
    __syncthreads();

    const unsigned long long bias =
        *reinterpret_cast<const unsigned long long*>(&sb[lane * 2]);

    unsigned long long acc[2][8];
    #pragma unroll
    for (int ry = 0; ry < 2; ++ry)
        #pragma unroll
        for (int rx = 0; rx < 8; ++rx)
            acc[ry][rx] = bias;

    const float* xb = x + ((size_t)b * NTOK + 1) * CH + c;
    const float* swp = &sw[lane * 2];

    unsigned long long rwA[14], rwB[14];

    auto load_win = [&](int riy, unsigned long long* rw) {
        const int iy = y0 - 3 + riy;
        const bool yok = ((unsigned)iy < (unsigned)HW);
        const float* row = xb + (size_t)iy * HW * CH;
        #pragma unroll
        for (int i = 0; i < 14; ++i) {
            const int xc = x0 - 3 + i;
            rw[i] = (yok && (unsigned)xc < (unsigned)HW)
                  ? *reinterpret_cast<const unsigned long long*>(&row[(size_t)xc * CH])
                  : 0ULL;
        }
    };

    auto compute = [&](int riy, const unsigned long long* rw) {
        #pragma unroll
        for (int ky = 0; ky < 7; ++ky) {
            const int ry = riy - ky;           // compile-time after full unroll
            if (ry == 0 || ry == 1) {
                #pragma unroll
                for (int kx = 0; kx < 7; ++kx) {
                    const unsigned long long wk =
                        *reinterpret_cast<const unsigned long long*>(
                            &swp[(ky * 7 + kx) * 64]);
                    #pragma unroll
                    for (int rx = 0; rx < 8; ++rx)
                        acc[ry][rx] = ffma2(rw[rx + kx], wk, acc[ry][rx]);
                }
            }
        }
    };

    // Software pipeline: prefetch row r+1 window before computing row r.
    load_win(0, rwA);
    #pragma unroll
    for (int r = 0; r < 8; ++r) {
        unsigned long long* cur = (r & 1) ? rwB : rwA;
        unsigned long long* nxt = (r & 1) ? rwA : rwB;
        if (r < 7) load_win(r + 1, nxt);
        compute(r, cur);
    }

    float* ob = out + ((size_t)b * NTOK + 1) * CH + c;
    #pragma unroll
    for (int ry = 0; ry < 2; ++ry)
        #pragma unroll
        for (int rx = 0; rx < 8; ++rx) {
            const size_t p = (size_t)(y0 + ry) * HW + (x0 + rx);
            *reinterpret_cast<unsigned long long*>(&ob[p * CH]) = acc[ry][rx];
        }
}

// ---------------------------------------------------------------------------
extern "C" void kernel_launch(void* const* d_in, const int* in_sizes, int n_in,
                              void* d_out, int out_size) {
    const float* x  = (const float*)d_in[0];
    const float* w7 = (const float*)d_in[1];
    const float* b7 = (const float*)d_in[2];
    const float* w5 = (const float*)d_in[3];
    const float* b5 = (const float*)d_in[4];
    const float* w3 = (const float*)d_in[5];
    const float* b3 = (const float*)d_in[6];
    float* out = (float*)d_out;

    ppeg_prep<<<132, 256>>>(w7, b7, w5, b5, w3, b3, x, out);
    dim3 grid(4, 4, 16 * 8);
    ppeg_conv<<<grid, 512>>>(x, out);
}